// round 9
// baseline (speedup 1.0000x reference)
#include <cuda_runtime.h>
#include <cuda_bf16.h>

// Scratch: exclusive prefix offsets of node_num (B up to 8192)
__device__ int g_off[8193];

// ---------------------------------------------------------------------------
// Kernel 1: single-block exclusive scan, 256 threads, warp-shuffle based.
// Thread t owns elements [t*items, (t+1)*items). Two barriers total.
// ---------------------------------------------------------------------------
__global__ __launch_bounds__(256)
void scan_kernel(const int* __restrict__ node_num, int B) {
    const int tid  = threadIdx.x;
    const int lane = tid & 31;
    const int warp = tid >> 5;
    const int items = (B + 255) >> 8;          // per-thread count (16 for B=4096)

    // thread-local serial scan (exclusive prefixes kept in regs, cap 32)
    int v[32];
    const int base = tid * items;
    int tsum = 0;
    for (int i = 0; i < items && i < 32; ++i) {
        int idx = base + i;
        int val = (idx < B) ? node_num[idx] : 0;
        v[i] = tsum;
        tsum += val;
    }

    // warp inclusive scan over thread sums
    int inc = tsum;
    #pragma unroll
    for (int off = 1; off < 32; off <<= 1) {
        int n = __shfl_up_sync(0xFFFFFFFFu, inc, off);
        if (lane >= off) inc += n;
    }

    __shared__ int wtot[8];
    if (lane == 31) wtot[warp] = inc;
    __syncthreads();

    // each thread sums preceding warp totals (8 values, serial)
    int wbase = 0;
    #pragma unroll
    for (int w = 0; w < 8; ++w)
        if (w < warp) wbase += wtot[w];

    const int excl = wbase + inc - tsum;       // exclusive prefix of this thread

    for (int i = 0; i < items && i < 32; ++i) {
        int idx = base + i;
        if (idx < B) g_off[idx] = excl + v[i];
    }
    if (tid == 255) g_off[B] = wbase + inc;
}

// ---------------------------------------------------------------------------
// Kernel 2: persistent fused segment-mean + tiny GEMM + sigmoid.
// Grid = 1184 CTAs (148 SM x 8); CTA processes segments cyclically.
// 256 threads; thread t owns float4 columns c..c+3, c = 4*(t&63).
// Unroll 2 over 4-row groups -> two LDG.128 in flight per thread.
// ---------------------------------------------------------------------------
__global__ __launch_bounds__(256, 8)
void segmean_kernel(const float* __restrict__ x,
                    const int*   __restrict__ node_num,
                    const float* __restrict__ W,     // [4,256]
                    const float* __restrict__ bias,  // [4]
                    float*       __restrict__ out,   // [B,4]
                    int B)
{
    const int t = threadIdx.x;
    const int warp = t >> 5;
    const int lane = t & 31;

    // this thread's W columns (loop-invariant)
    const int c4 = (t & 63) << 2;
    const float4 w0 = *reinterpret_cast<const float4*>(W + c4);
    const float4 w1 = *reinterpret_cast<const float4*>(W + 256 + c4);
    const float4 w2 = *reinterpret_cast<const float4*>(W + 512 + c4);
    const float4 w3 = *reinterpret_cast<const float4*>(W + 768 + c4);

    __shared__ float part[8][4];

    for (int b = blockIdx.x; b < B; b += gridDim.x) {
        const int cnt   = __ldg(&node_num[b]);
        const int start = g_off[b];

        const float4* p = reinterpret_cast<const float4*>(x + (size_t)start * 256) + t;

        float4 sA = make_float4(0.f, 0.f, 0.f, 0.f);
        float4 sB = make_float4(0.f, 0.f, 0.f, 0.f);

        const int nIter = cnt >> 2;             // 4-row groups
        int i = 0;
        for (; i + 2 <= nIter; i += 2) {
            float4 a = p[0];
            float4 c = p[256];
            sA.x += a.x; sA.y += a.y; sA.z += a.z; sA.w += a.w;
            sB.x += c.x; sB.y += c.y; sB.z += c.z; sB.w += c.w;
            p += 512;
        }
        if (nIter & 1) {
            float4 a = p[0];
            sA.x += a.x; sA.y += a.y; sA.z += a.z; sA.w += a.w;
            p += 256;
        }
        // tail rows: (cnt & 3) * 64 float4 elements, flat (columns preserved)
        const int tailN = (cnt & 3) << 6;
        if (t < tailN) {
            float4 a = p[0];
            sB.x += a.x; sB.y += a.y; sB.z += a.z; sB.w += a.w;
        }

        float4 s;
        s.x = sA.x + sB.x;
        s.y = sA.y + sB.y;
        s.z = sA.z + sB.z;
        s.w = sA.w + sB.w;

        float p0 = s.x * w0.x + s.y * w0.y + s.z * w0.z + s.w * w0.w;
        float p1 = s.x * w1.x + s.y * w1.y + s.z * w1.z + s.w * w1.w;
        float p2 = s.x * w2.x + s.y * w2.y + s.z * w2.z + s.w * w2.w;
        float p3 = s.x * w3.x + s.y * w3.y + s.z * w3.z + s.w * w3.w;

        #pragma unroll
        for (int off = 16; off > 0; off >>= 1) {
            p0 += __shfl_down_sync(0xFFFFFFFFu, p0, off);
            p1 += __shfl_down_sync(0xFFFFFFFFu, p1, off);
            p2 += __shfl_down_sync(0xFFFFFFFFu, p2, off);
            p3 += __shfl_down_sync(0xFFFFFFFFu, p3, off);
        }

        if (lane == 0) {
            part[warp][0] = p0;
            part[warp][1] = p1;
            part[warp][2] = p2;
            part[warp][3] = p3;
        }
        __syncthreads();

        if (t < 4) {
            float acc = 0.f;
            #pragma unroll
            for (int w = 0; w < 8; ++w) acc += part[w][t];
            acc = bias[t] + acc / (float)cnt;
            out[(size_t)b * 4 + t] = 1.0f / (1.0f + __expf(-acc));
        }
        __syncthreads();   // protect part[][] before next iteration
    }
}

extern "C" void kernel_launch(void* const* d_in, const int* in_sizes, int n_in,
                              void* d_out, int out_size) {
    const float* x        = (const float*)d_in[0];
    const int*   node_num = (const int*)  d_in[1];
    const float* W        = (const float*)d_in[2];
    const float* bias     = (const float*)d_in[3];
    float*       out      = (float*)d_out;

    const int B = in_sizes[1];   // 4096 segments

    scan_kernel<<<1, 256>>>(node_num, B);

    int grid = 148 * 8;          // one full persistent wave
    if (grid > B) grid = B;
    segmean_kernel<<<grid, 256>>>(x, node_num, W, bias, out, B);
}

// round 10
// speedup vs baseline: 1.3422x; 1.3422x over previous
#include <cuda_runtime.h>
#include <cuda_bf16.h>

// ---------------------------------------------------------------------------
// Single fused kernel: one CTA per segment.
//   Prologue: self-compute segment offset (sum of node_num[0..b)) via
//             coalesced stride-256 loads (L2-hot, 16KB table) + block reduce.
//   Mainloop: thread t owns float4 columns 4*(t&63).. ; 256 threads x float4
//             = 4 rows per iter, unroll 2 -> two LDG.128 (evict-first) in
//             flight per thread.
//   Epilogue: partial dots with W, warp shuffle reduce, smem combine,
//             sigmoid, 4-float store.
// ---------------------------------------------------------------------------
__global__ __launch_bounds__(256, 8)
void segmean_kernel(const float* __restrict__ x,
                    const int*   __restrict__ node_num,
                    const float* __restrict__ W,     // [4,256]
                    const float* __restrict__ bias,  // [4]
                    float*       __restrict__ out,   // [B,4]
                    int B)
{
    const int b = blockIdx.x;
    const int t = threadIdx.x;
    const int warp = t >> 5;
    const int lane = t & 31;

    // ---- self-scan: start = sum node_num[0..b) ----
    int partial = 0;
    for (int i = t; i < b; i += 256)
        partial += __ldg(&node_num[i]);

    #pragma unroll
    for (int off = 16; off > 0; off >>= 1)
        partial += __shfl_down_sync(0xFFFFFFFFu, partial, off);

    __shared__ int wsum[8];
    if (lane == 0) wsum[warp] = partial;
    __syncthreads();
    if (t == 0) {
        int s = 0;
        #pragma unroll
        for (int w = 0; w < 8; ++w) s += wsum[w];
        wsum[0] = s;
    }
    __syncthreads();
    const int start = wsum[0];
    const int cnt   = __ldg(&node_num[b]);

    // ---- streaming column sums ----
    const float4* p = reinterpret_cast<const float4*>(x + (size_t)start * 256) + t;

    float4 sA = make_float4(0.f, 0.f, 0.f, 0.f);
    float4 sB = make_float4(0.f, 0.f, 0.f, 0.f);

    const int nIter = cnt >> 2;             // 4-row groups
    int i = 0;
    for (; i + 2 <= nIter; i += 2) {
        float4 a = __ldcs(p);
        float4 c = __ldcs(p + 256);
        sA.x += a.x; sA.y += a.y; sA.z += a.z; sA.w += a.w;
        sB.x += c.x; sB.y += c.y; sB.z += c.z; sB.w += c.w;
        p += 512;
    }
    if (nIter & 1) {
        float4 a = __ldcs(p);
        sA.x += a.x; sA.y += a.y; sA.z += a.z; sA.w += a.w;
        p += 256;
    }
    // tail rows: (cnt & 3) * 64 float4 elements, flat (column ownership
    // preserved because 1024 floats == 0 mod 256)
    const int tailN = (cnt & 3) << 6;
    if (t < tailN) {
        float4 a = __ldcs(p);
        sB.x += a.x; sB.y += a.y; sB.z += a.z; sB.w += a.w;
    }

    float4 s;
    s.x = sA.x + sB.x;
    s.y = sA.y + sB.y;
    s.z = sA.z + sB.z;
    s.w = sA.w + sB.w;

    // ---- partial dots with each W row over this thread's 4 columns ----
    const int c4 = (t & 63) << 2;
    const float4 w0 = *reinterpret_cast<const float4*>(W + c4);
    const float4 w1 = *reinterpret_cast<const float4*>(W + 256 + c4);
    const float4 w2 = *reinterpret_cast<const float4*>(W + 512 + c4);
    const float4 w3 = *reinterpret_cast<const float4*>(W + 768 + c4);

    float p0 = s.x * w0.x + s.y * w0.y + s.z * w0.z + s.w * w0.w;
    float p1 = s.x * w1.x + s.y * w1.y + s.z * w1.z + s.w * w1.w;
    float p2 = s.x * w2.x + s.y * w2.y + s.z * w2.z + s.w * w2.w;
    float p3 = s.x * w3.x + s.y * w3.y + s.z * w3.z + s.w * w3.w;

    #pragma unroll
    for (int off = 16; off > 0; off >>= 1) {
        p0 += __shfl_down_sync(0xFFFFFFFFu, p0, off);
        p1 += __shfl_down_sync(0xFFFFFFFFu, p1, off);
        p2 += __shfl_down_sync(0xFFFFFFFFu, p2, off);
        p3 += __shfl_down_sync(0xFFFFFFFFu, p3, off);
    }

    __shared__ float part[8][4];
    if (lane == 0) {
        part[warp][0] = p0;
        part[warp][1] = p1;
        part[warp][2] = p2;
        part[warp][3] = p3;
    }
    __syncthreads();

    if (t < 4) {
        float acc = 0.f;
        #pragma unroll
        for (int w = 0; w < 8; ++w) acc += part[w][t];
        acc = bias[t] + acc / (float)cnt;
        out[(size_t)b * 4 + t] = 1.0f / (1.0f + __expf(-acc));
    }
}

extern "C" void kernel_launch(void* const* d_in, const int* in_sizes, int n_in,
                              void* d_out, int out_size) {
    const float* x        = (const float*)d_in[0];
    const int*   node_num = (const int*)  d_in[1];
    const float* W        = (const float*)d_in[2];
    const float* bias     = (const float*)d_in[3];
    float*       out      = (float*)d_out;

    const int B = in_sizes[1];   // 4096 segments

    segmean_kernel<<<B, 256>>>(x, node_num, W, bias, out, B);
}